// round 1
// baseline (speedup 1.0000x reference)
#include <cuda_runtime.h>
#include <math.h>

#define E 128
#define C 64
#define TILE_N 128
#define THREADS 256
#define SC_STRIDE 68    // 128x68 centroid tile, k-major (16B-aligned float4 rows, modest conflicts)
#define SN_STRIDE 129   // 128x129 node tile, k-major (odd stride -> conflict-free transpose stores)
#define EPSV 1e-5f

__device__ float g_scratch[C + 1];   // [0..63] per-centroid masked-dist sums, [64] mask sum

__global__ void cd_zero_kernel() {
    int t = threadIdx.x;
    if (t < C + 1) g_scratch[t] = 0.0f;
}

__global__ __launch_bounds__(THREADS, 2)
void cd_main_kernel(const float* __restrict__ node_repr,
                    const float* __restrict__ mask,
                    const float* __restrict__ cent,
                    float* __restrict__ node_out, int N) {
    extern __shared__ float smem[];
    float* sn     = smem;                       // [E][SN_STRIDE]
    float* sc     = sn + E * SN_STRIDE;         // [E][SC_STRIDE]
    float* s_su   = sc + E * SC_STRIDE;         // [TILE_N]
    float* s_sv   = s_su + TILE_N;              // [C]
    float* s_mask = s_sv + C;                   // [TILE_N]
    float* s_red  = s_mask + TILE_N;            // [C]

    const int tid = threadIdx.x;
    const int n0  = blockIdx.x * TILE_N;

    // Centroids: global row-major [c][k] -> smem k-major [k][c]. Coalesced reads.
    for (int idx = tid; idx < C * E; idx += THREADS) {
        int k = idx & (E - 1);
        int c = idx >> 7;
        sc[k * SC_STRIDE + c] = cent[idx];
    }
    // Node tile: global [n][k] -> smem k-major [k][i]. Coalesced reads, conflict-free stores.
    for (int idx = tid; idx < TILE_N * E; idx += THREADS) {
        int k = idx & (E - 1);
        int i = idx >> 7;
        int n = n0 + i;
        sn[k * SN_STRIDE + i] = (n < N) ? node_repr[(size_t)n * E + k] : 0.0f;
    }
    if (tid < TILE_N) {
        int n = n0 + tid;
        s_mask[tid] = (n < N) ? mask[n] : 0.0f;
    }
    if (tid < C) s_red[tid] = 0.0f;
    __syncthreads();

    // Squared norms (threads 0..127 do su, 128..191 do sv, concurrently; both conflict-free)
    if (tid < TILE_N) {
        float s = 0.f;
        #pragma unroll 8
        for (int k = 0; k < E; k++) {
            float v = sn[k * SN_STRIDE + tid];
            s += v * v;
        }
        s_su[tid] = s;
    } else if (tid < TILE_N + C) {
        int c = tid - TILE_N;
        float s = 0.f;
        #pragma unroll 8
        for (int k = 0; k < E; k++) {
            float v = sc[k * SC_STRIDE + c];
            s += v * v;
        }
        s_sv[c] = s;
    }
    __syncthreads();

    // Register tile: 8 nodes x 4 centroids per thread. tx in [0,16) -> centroids, ty in [0,16) -> nodes.
    const int tx = tid & 15;
    const int ty = tid >> 4;

    float acc[8][4];
    #pragma unroll
    for (int i = 0; i < 8; i++)
        #pragma unroll
        for (int j = 0; j < 4; j++) acc[i][j] = 0.f;

    const float* snp = sn + 8 * ty;
    const float* scp = sc + 4 * tx;

    #pragma unroll 4
    for (int k = 0; k < E; k++) {
        float4 cv = *(const float4*)(scp + k * SC_STRIDE);
        #pragma unroll
        for (int i = 0; i < 8; i++) {
            float nv = snp[k * SN_STRIDE + i];
            acc[i][0] = fmaf(nv, cv.x, acc[i][0]);
            acc[i][1] = fmaf(nv, cv.y, acc[i][1]);
            acc[i][2] = fmaf(nv, cv.z, acc[i][2]);
            acc[i][3] = fmaf(nv, cv.w, acc[i][3]);
        }
    }

    // Epilogue: Poincare distance + masked output + per-centroid partial sums
    float sv_r[4];
    #pragma unroll
    for (int j = 0; j < 4; j++) sv_r[j] = s_sv[4 * tx + j];

    float psum[4] = {0.f, 0.f, 0.f, 0.f};

    #pragma unroll
    for (int i = 0; i < 8; i++) {
        int ln = 8 * ty + i;
        int n  = n0 + ln;
        if (n < N) {
            float su = s_su[ln];
            float m  = s_mask[ln];
            float4 o;
            float* op = &o.x;
            #pragma unroll
            for (int j = 0; j < 4; j++) {
                float sq    = fmaxf(su + sv_r[j] - 2.f * acc[i][j], 0.f);
                float denom = fmaxf((1.f - su) * (1.f - sv_r[j]), EPSV);
                float arg   = fmaxf(1.f + 2.f * sq / denom, 1.f + EPSV);
                float d     = acoshf(arg) * m;
                op[j] = d;
                psum[j] += d;
            }
            *(float4*)(node_out + (size_t)n * C + 4 * tx) = o;
        }
    }

    #pragma unroll
    for (int j = 0; j < 4; j++) atomicAdd(&s_red[4 * tx + j], psum[j]);
    __syncthreads();

    if (tid < C) atomicAdd(&g_scratch[tid], s_red[tid]);
    if (tid == 0) {
        float ms = 0.f;
        #pragma unroll 8
        for (int i = 0; i < TILE_N; i++) ms += s_mask[i];
        atomicAdd(&g_scratch[C], ms);
    }
}

__global__ void cd_final_kernel(float* __restrict__ out) {
    int c = threadIdx.x;
    if (c < C) out[c] = g_scratch[c] / g_scratch[C];
}

extern "C" void kernel_launch(void* const* d_in, const int* in_sizes, int n_in,
                              void* d_out, int out_size) {
    const float* node_repr = (const float*)d_in[0];
    const float* maskp     = (const float*)d_in[1];
    const float* cent      = (const float*)d_in[2];
    float* out = (float*)d_out;

    int N = in_sizes[1];               // mask element count == node count
    float* node_out = out + C;         // tuple order: graph [C] first, then node [N*C]

    int smem_bytes = (E * SN_STRIDE + E * SC_STRIDE + TILE_N + C + TILE_N + C) * (int)sizeof(float);
    cudaFuncSetAttribute(cd_main_kernel, cudaFuncAttributeMaxDynamicSharedMemorySize, smem_bytes);

    cd_zero_kernel<<<1, 128>>>();
    int blocks = (N + TILE_N - 1) / TILE_N;
    cd_main_kernel<<<blocks, THREADS, smem_bytes>>>(node_repr, maskp, cent, node_out, N);
    cd_final_kernel<<<1, 64>>>(out);
}